// round 8
// baseline (speedup 1.0000x reference)
#include <cuda_runtime.h>

#define NX 1024
#define NY 1024
#define NB 8
#define CH (NX*NY)
#define ROWS 4
#define STRIPS (NY/ROWS)        // 256
#define NBLOCKS (STRIPS*NB)     // 2048

// Physics constants
#define PR     0.71f
#define RA_PR  710.0f
#define HA2_PR 71.0f
#define PR_DA  7.1f
#define DIFF_C 1.6666666666666667f
#define QQ     0.1f
#define DTINV  100.0f
#define NPTS   8388608.0

__device__ double   g_partials[NBLOCKS];
__device__ unsigned g_count = 0;   // atomicInc wraps -> graph-replay safe

// x-halo via warp shuffle; warp-boundary lanes patch from global (L1 hit).
__device__ __forceinline__ void halo(float4 c, const float* __restrict__ rowp,
                                     int tid, int lane,
                                     float& lz, float& lw, float& rx, float& ry)
{
    lw = __shfl_up_sync(0xFFFFFFFFu, c.w, 1);
    lz = __shfl_up_sync(0xFFFFFFFFu, c.z, 1);
    rx = __shfl_down_sync(0xFFFFFFFFu, c.x, 1);
    ry = __shfl_down_sync(0xFFFFFFFFu, c.y, 1);
    if (lane == 0 && tid != 0) {
        float2 h = *(const float2*)(rowp + tid * 4 - 2);
        lz = h.x; lw = h.y;
    }
    if (lane == 31 && tid != 255) {
        float2 h = *(const float2*)(rowp + tid * 4 + 4);
        rx = h.x; ry = h.y;
    }
}

// x first+second tgrad for 4 points; E0..E7 = values at x0-2..x0+5. (verified)
__device__ __forceinline__ void xderiv(float4 c, float lz, float lw, float rx, float ry,
                                       int tid, float* dx, float* dxx)
{
    float E0 = lz, E1 = lw, E2 = c.x, E3 = c.y, E4 = c.z, E5 = c.w, E6 = rx, E7 = ry;
    if (tid == 0) {
        dx[0]  = E3 - E2;
        dx[1]  = 0.5f * (E4 - E2);
        dxx[0] = 0.5f * E4 - E3 + 0.5f * E2;
        dxx[1] = 0.25f * E5 - 0.75f * E3 + 0.5f * E2;
    } else {
        dx[0]  = 0.5f * (E3 - E1);
        dx[1]  = 0.5f * (E4 - E2);
        dxx[0] = 0.25f * (E4 - 2.0f * E2 + E0);
        dxx[1] = 0.25f * (E5 - 2.0f * E3 + E1);
    }
    if (tid == 255) {
        dx[2]  = 0.5f * (E5 - E3);
        dx[3]  = E5 - E4;
        dxx[2] = 0.5f * E5 - 0.75f * E4 + 0.25f * E2;
        dxx[3] = 0.5f * E5 - E4 + 0.5f * E3;
    } else {
        dx[2]  = 0.5f * (E5 - E3);
        dx[3]  = 0.5f * (E6 - E4);
        dxx[2] = 0.25f * (E6 - 2.0f * E4 + E2);
        dxx[3] = 0.25f * (E7 - 2.0f * E5 + E3);
    }
}

// dx only (for P channel)
__device__ __forceinline__ void xderiv1(float4 c, float lz, float lw, float rx, float ry,
                                        int tid, float* dx)
{
    float E1 = lw, E2 = c.x, E3 = c.y, E4 = c.z, E5 = c.w, E6 = rx;
    dx[1] = 0.5f * (E4 - E2);
    dx[2] = 0.5f * (E5 - E3);
    dx[0] = (tid == 0)   ? (E3 - E2) : 0.5f * (E3 - E1);
    dx[3] = (tid == 255) ? (E5 - E4) : 0.5f * (E6 - E4);
}

// Full derivative set for one channel row (5 y-row loads; overlap rows are L1 hits)
struct CD { float v[4], dx[4], dxx[4], dy[4], dyy[4]; };

__device__ __forceinline__ void chan(const float* __restrict__ chp,
                                     int tid, int lane, int y, int x0,
                                     int rM, int rP, float s1,
                                     int rA, int rB, float cA, float cC, float cB,
                                     CD& d)
{
    const float* rowp = chp + (size_t)y * NX;
    float4 c  = *(const float4*)(rowp + x0);
    float4 m  = *(const float4*)(chp + (size_t)rM * NX + x0);
    float4 p  = *(const float4*)(chp + (size_t)rP * NX + x0);
    float4 a  = *(const float4*)(chp + (size_t)rA * NX + x0);
    float4 bb = *(const float4*)(chp + (size_t)rB * NX + x0);
    float lz, lw, rx, ry;
    halo(c, rowp, tid, lane, lz, lw, rx, ry);
    xderiv(c, lz, lw, rx, ry, tid, d.dx, d.dxx);
    const float* C  = (const float*)&c;
    const float* M  = (const float*)&m;  const float* P_ = (const float*)&p;
    const float* A  = (const float*)&a;  const float* B_ = (const float*)&bb;
#pragma unroll
    for (int j = 0; j < 4; j++) {
        d.v[j]   = C[j];
        d.dy[j]  = s1 * (P_[j] - M[j]);
        d.dyy[j] = cA * A[j] + cC * C[j] + cB * B_[j];
    }
}

__global__ __launch_bounds__(256, 4)
void physics_loss_kernel(const float* __restrict__ fno, const float* __restrict__ fne,
                         float* __restrict__ out)
{
    const int tid  = threadIdx.x;
    const int lane = tid & 31;
    const int strip = blockIdx.x;
    const int b    = blockIdx.y;
    const int y0   = strip * ROWS;
    const int x0   = tid * 4;

    const size_t base = (size_t)b * 4 * CH;
    const float* __restrict__ Uc = fne + base;
    const float* __restrict__ Vc = fne + base + CH;
    const float* __restrict__ Tc = fne + base + 2 * (size_t)CH;
    const float* __restrict__ Pc = fne + base + 3 * (size_t)CH;

    double dacc = 0.0;

#pragma unroll 1
    for (int y = y0; y < y0 + ROWS; y++) {
        const int   rM = (y > 0) ? y - 1 : 0;
        const int   rP = (y < NY - 1) ? y + 1 : NY - 1;
        const float s1 = (y == 0 || y == NY - 1) ? 1.0f : 0.5f;

        int rA, rB; float cA, cC, cB;
        if      (y == 0)      { rA = 2;      cA = 0.5f;  cC = 0.5f;   rB = 1;      cB = -1.0f; }
        else if (y == 1)      { rA = 0;      cA = 0.5f;  cC = -0.75f; rB = 3;      cB = 0.25f; }
        else if (y == NY - 2) { rA = NY - 4; cA = 0.25f; cC = -0.75f; rB = NY - 1; cB = 0.5f;  }
        else if (y == NY - 1) { rA = NY - 3; cA = 0.5f;  cC = 0.5f;   rB = NY - 2; cB = -1.0f; }
        else                  { rA = y - 2;  cA = 0.25f; cC = -0.5f;  rB = y + 2;  cB = 0.25f; }

        const size_t rowo = (size_t)y * NX + x0;
        float rowacc = 0.0f;

        // ---- P pass: pdx, pdy ----
        float pdx[4], pdy[4];
        {
            const float* rowp = Pc + (size_t)y * NX;
            float4 c = *(const float4*)(rowp + x0);
            float4 m = *(const float4*)(Pc + (size_t)rM * NX + x0);
            float4 p = *(const float4*)(Pc + (size_t)rP * NX + x0);
            float lz, lw, rx, ry;
            halo(c, rowp, tid, lane, lz, lw, rx, ry);
            xderiv1(c, lz, lw, rx, ry, tid, pdx);
            const float* M = (const float*)&m; const float* P_ = (const float*)&p;
#pragma unroll
            for (int j = 0; j < 4; j++) pdy[j] = s1 * (P_[j] - M[j]);
        }

        // f_now U, V (needed across passes)
        float4 uo4 = __ldcs((const float4*)(fno + base + rowo));
        float4 vo4 = __ldcs((const float4*)(fno + base + CH + rowo));
        const float* Uo = (const float*)&uo4;
        const float* Vo = (const float*)&vo4;

        float cont[4], resy[4];

        // ---- U pass: resx done (consumes pdx), keep cont ----
        {
            CD d;
            chan(Uc, tid, lane, y, x0, rM, rP, s1, rA, rB, cA, cC, cB, d);
#pragma unroll
            for (int j = 0; j < 4; j++) {
                float Un = d.v[j];
                float resx = (Un - Uo[j]) * DTINV + Un * d.dx[j] + Vo[j] * d.dy[j]
                             + pdx[j] - PR * (d.dxx[j] + d.dyy[j]) + PR_DA * Un;
                rowacc += resx * resx;
                cont[j] = d.dx[j];
            }
        }
        // ---- V pass: cont done, resy started (consumes pdy) ----
        {
            CD d;
            chan(Vc, tid, lane, y, x0, rM, rP, s1, rA, rB, cA, cC, cB, d);
#pragma unroll
            for (int j = 0; j < 4; j++) {
                float Vn = d.v[j];
                float cj = cont[j] + d.dy[j];
                rowacc += cj * cj;
                resy[j] = (Vn - Vo[j]) * DTINV + Uo[j] * d.dx[j] + Vn * d.dy[j]
                          + pdy[j] - PR * (d.dxx[j] + d.dyy[j]) + (HA2_PR + PR_DA) * Vn;
            }
        }
        // ---- T pass: resy + rest done ----
        {
            CD d;
            chan(Tc, tid, lane, y, x0, rM, rP, s1, rA, rB, cA, cC, cB, d);
            float4 to4 = __ldcs((const float4*)(fno + base + 2 * (size_t)CH + rowo));
            const float* To = (const float*)&to4;
#pragma unroll
            for (int j = 0; j < 4; j++) {
                float Tn = d.v[j];
                float ry2 = resy[j] - RA_PR * Tn;
                rowacc += ry2 * ry2;
                float rest = (Tn - To[j]) * DTINV + Uo[j] * d.dx[j] + Vo[j] * d.dy[j]
                             - DIFF_C * (d.dxx[j] + d.dyy[j]) - QQ * Tn;
                rowacc += rest * rest;
            }
        }

        dacc += (double)rowacc;
    }

    // block reduction
#pragma unroll
    for (int o = 16; o > 0; o >>= 1)
        dacc += __shfl_xor_sync(0xFFFFFFFFu, dacc, o);

    __shared__ double ws[8];
    __shared__ bool   is_last;
    if (lane == 0) ws[tid >> 5] = dacc;
    __syncthreads();

    const int bid = blockIdx.y * STRIPS + blockIdx.x;
    if (tid == 0) {
        double s = 0.0;
#pragma unroll
        for (int k = 0; k < 8; k++) s += ws[k];
        g_partials[bid] = s;
        __threadfence();
        unsigned prev = atomicInc(&g_count, NBLOCKS - 1);
        is_last = (prev == NBLOCKS - 1);
    }
    __syncthreads();

    if (is_last) {
        double v = 0.0;
#pragma unroll
        for (int k = 0; k < NBLOCKS / 256; k++)
            v += g_partials[tid + k * 256];
#pragma unroll
        for (int o = 16; o > 0; o >>= 1)
            v += __shfl_xor_sync(0xFFFFFFFFu, v, o);
        if (lane == 0) ws[tid >> 5] = v;
        __syncthreads();
        if (tid == 0) {
            double s = 0.0;
#pragma unroll
            for (int k = 0; k < 8; k++) s += ws[k];
            double t = s * 1e-4 / NPTS;
            if (t < 1e-10) t = 1e-10;
            if (t > 1.0)   t = 1.0;
            out[0] = (float)t;
        }
    }
}

extern "C" void kernel_launch(void* const* d_in, const int* in_sizes, int n_in,
                              void* d_out, int out_size)
{
    const float* f_now  = (const float*)d_in[0];
    const float* f_next = (const float*)d_in[1];

    dim3 grid(STRIPS, NB);
    physics_loss_kernel<<<grid, 256>>>(f_now, f_next, (float*)d_out);
}